// round 15
// baseline (speedup 1.0000x reference)
#include <cuda_runtime.h>

typedef unsigned long long u64;

#define NQ     10
#define NGEN   4
#define QDEPTH 6
#define SIGN2  0x8000000080000000ull

// ---- packed f32x2 helpers (SASS FFMA2 — PTX-only on sm_103a) ----
__device__ __forceinline__ u64 fma2(u64 a, u64 b, u64 c) {
    u64 d; asm("fma.rn.f32x2 %0, %1, %2, %3;" : "=l"(d) : "l"(a), "l"(b), "l"(c)); return d;
}
__device__ __forceinline__ u64 pack2(float lo, float hi) {
    u64 d; asm("mov.b64 %0, {%1, %2};" : "=l"(d) : "f"(lo), "f"(hi)); return d;
}
__device__ __forceinline__ void unpack2(u64 v, float& lo, float& hi) {
    asm("mov.b64 {%0, %1}, %2;" : "=f"(lo), "=f"(hi) : "l"(v));
}
__device__ __forceinline__ u64 swap32(u64 v) { return (v << 32) | (v >> 32); }

// RY shear (rotation phi): nt=(-t,-t), sn=(s,s); t=tan(phi/2), s=sin(phi). 3 fma2/pair.
template<int M>
__device__ __forceinline__ void ry16(u64 (&v)[16], u64 nt, u64 sn) {
    #pragma unroll
    for (int k = 0; k < 16; ++k) if (!(k & M)) {
        const int j = k | M;
        u64 a0 = v[k], a1 = v[j];
        a0 = fma2(nt, a1, a0);
        a1 = fma2(sn, a0, a1);
        a0 = fma2(nt, a1, a0);
        v[k] = a0; v[j] = a1;
    }
}

// RX shear (verified in R13 bench): rnt=(t,-t), rsn=(-s,s).
template<int M>
__device__ __forceinline__ void rx16(u64 (&v)[16], u64 rnt, u64 rsn) {
    #pragma unroll
    for (int k = 0; k < 16; ++k) if (!(k & M)) {
        const int j = k | M;
        u64 u = v[k], p = swap32(v[j]);
        u = fma2(rnt, p, u);
        p = fma2(rsn, u, p);
        u = fma2(rnt, p, u);
        v[k] = u; v[j] = swap32(p);
    }
}

// per-thread partial of <X> on a register wire: sum_k v[k]*v[k^M] (re+im in halves)
template<int M>
__device__ __forceinline__ float exv16(const u64 (&v)[16]) {
    u64 acc0 = 0ull, acc1 = 0ull;
    #pragma unroll
    for (int k = 0; k < 16; k += 2) {
        acc0 = fma2(v[k + 0], v[(k + 0) ^ M], acc0);
        acc1 = fma2(v[k + 1], v[(k + 1) ^ M], acc1);
    }
    float l0, h0, l1, h1;
    unpack2(acc0, l0, h0); unpack2(acc1, l1, h1);
    return (l0 + h0) + (l1 + h1);
}

// P2 permute offset for reg index k: i-bits k0->+1, k1->+2, k2->bit8(+256,pad+16), k3->bit9(+512,pad+32)
#define OFF2(k) (((k) & 3) + (((k) & 4) ? 272 : 0) + (((k) & 8) ? 544 : 0))

// ===== One block (64 threads = 2 warps) per circuit (b, g). =====
// Phase mappings of global amp index i (wire q <-> bit 9-q):
//  P0: i = w<<9 | lane<<4 | k          (reg bits 3..0 = wires 6,7,8,9)
//  P1: i = w<<9 | (lane>>4)<<8 | k<<4 | (lane&15)   (reg bits = wires 2,3,4,5)
//  P2: i = (k>>3)<<9 | ((k>>2)&1)<<8 | w<<7 | lane<<2 | (k&3)  (k3,k2 = wires 0,1)
// Padded smem address: pad(i) = i + (i>>4).
__global__ void __launch_bounds__(64, 10)
qgen2w(const float* __restrict__ noise,
       const float* __restrict__ qp,
       float* __restrict__ out, int batch)
{
    __shared__ u64 tile[1088];
    __shared__ u64 TNT[64], TSN[64];                 // tail RY shear consts (60 used)
    __shared__ u64 YN[16], YS[16], RN[16], RS[16];   // init RY / RX shear consts
    __shared__ float red[20];

    const int tid  = threadIdx.x;
    const int w    = tid >> 5;
    const int lane = tid & 31;
    const int cid  = blockIdx.x;
    if (cid >= batch * NGEN) return;
    const int b = cid >> 2;
    const int g = cid & 3;

    // ---- lane-parallel const precompute (pre-packed u64) ----
    // RY(theta) rotates by phi=theta/2: t=tan(theta/4), s=sin(theta/2)=2 s4 c4
    if (tid < QDEPTH * NQ) {
        float a = qp[g * (QDEPTH * NQ) + tid];
        float s4, c4; __sincosf(0.25f * a, &s4, &c4);
        float tt = __fdividef(s4, c4);
        float ss = 2.0f * s4 * c4;
        TNT[tid] = pack2(-tt, -tt);
        TSN[tid] = pack2(ss, ss);
    }
    if (tid < NQ) {
        float a = noise[(size_t)b * NQ + tid];
        float s4, c4; __sincosf(0.25f * a, &s4, &c4);
        float tt = __fdividef(s4, c4);
        float ss = 2.0f * s4 * c4;
        YN[tid] = pack2(-tt, -tt); YS[tid] = pack2(ss, ss);
        RN[tid] = pack2(tt, -tt);  RS[tid] = pack2(-ss, ss);
    }

    // CZ-chain sign mask in P2 mapping: bit k = parity(popc(i & i>>1))
    unsigned czm = 0;
    #pragma unroll
    for (int k = 0; k < 16; ++k) {
        unsigned i = (unsigned)(((k >> 3) & 1) << 9) | (unsigned)(((k >> 2) & 1) << 8)
                   | (unsigned)(w << 7) | (unsigned)(lane << 2) | (unsigned)(k & 3);
        czm |= (unsigned)(__popc(i & (i >> 1)) & 1) << k;
    }

    // per-thread padded base addresses for each phase
    const int base0 = w * 544 + lane * 17;
    const int base1 = w * 544 + (lane >> 4) * 272 + (lane & 15);
    const int base2 = w * 136 + lane * 4 + (lane >> 2);

    __syncthreads();   // consts visible

    u64 v[16];
    #pragma unroll
    for (int k = 0; k < 16; ++k) v[k] = 0ull;
    if (tid == 0) v[0] = pack2(1.0f, 0.0f);   // |0..0> at P0 index 0

    // permutes (write current phase, read next phase)
    #define PERM01() do { __syncthreads();                                   \
        _Pragma("unroll") for (int k = 0; k < 16; ++k) tile[base0 + k] = v[k]; \
        __syncthreads();                                                     \
        _Pragma("unroll") for (int k = 0; k < 16; ++k) v[k] = tile[base1 + 17 * k]; } while (0)
    #define PERM12() do { __syncthreads();                                   \
        _Pragma("unroll") for (int k = 0; k < 16; ++k) tile[base1 + 17 * k] = v[k]; \
        __syncthreads();                                                     \
        _Pragma("unroll") for (int k = 0; k < 16; ++k) v[k] = tile[base2 + OFF2(k)]; } while (0)
    #define PERM20() do { __syncthreads();                                   \
        _Pragma("unroll") for (int k = 0; k < 16; ++k) tile[base2 + OFF2(k)] = v[k]; \
        __syncthreads();                                                     \
        _Pragma("unroll") for (int k = 0; k < 16; ++k) v[k] = tile[base0 + k]; } while (0)

    // ---- init: RY(n_q)+RX(n_q), per phase ----
    ry16<8>(v, YN[6], YS[6]); rx16<8>(v, RN[6], RS[6]);   // P0: wires 6..9
    ry16<4>(v, YN[7], YS[7]); rx16<4>(v, RN[7], RS[7]);
    ry16<2>(v, YN[8], YS[8]); rx16<2>(v, RN[8], RS[8]);
    ry16<1>(v, YN[9], YS[9]); rx16<1>(v, RN[9], RS[9]);
    PERM01();
    ry16<8>(v, YN[2], YS[2]); rx16<8>(v, RN[2], RS[2]);   // P1: wires 2..5
    ry16<4>(v, YN[3], YS[3]); rx16<4>(v, RN[3], RS[3]);
    ry16<2>(v, YN[4], YS[4]); rx16<2>(v, RN[4], RS[4]);
    ry16<1>(v, YN[5], YS[5]); rx16<1>(v, RN[5], RS[5]);
    PERM12();
    ry16<8>(v, YN[0], YS[0]); rx16<8>(v, RN[0], RS[0]);   // P2: wires 0,1
    ry16<4>(v, YN[1], YS[1]); rx16<4>(v, RN[1], RS[1]);
    PERM20();

    // ---- layers ----
    #pragma unroll
    for (int l = 0; l < QDEPTH; ++l) {
        const int o = l * NQ;
        ry16<8>(v, TNT[o + 6], TSN[o + 6]);   // P0: wires 6..9
        ry16<4>(v, TNT[o + 7], TSN[o + 7]);
        ry16<2>(v, TNT[o + 8], TSN[o + 8]);
        ry16<1>(v, TNT[o + 9], TSN[o + 9]);
        PERM01();
        ry16<8>(v, TNT[o + 2], TSN[o + 2]);   // P1: wires 2..5
        ry16<4>(v, TNT[o + 3], TSN[o + 3]);
        ry16<2>(v, TNT[o + 4], TSN[o + 4]);
        ry16<1>(v, TNT[o + 5], TSN[o + 5]);
        PERM12();
        ry16<8>(v, TNT[o + 0], TSN[o + 0]);   // P2: wires 0,1
        ry16<4>(v, TNT[o + 1], TSN[o + 1]);
        #pragma unroll
        for (int k = 0; k < 16; ++k)
            if (czm & (1u << k)) v[k] ^= SIGN2;   // CZ-chain diagonal
        PERM20();
    }

    // ---- expectations (state in P0) ----
    float e[10];
    e[6] = exv16<8>(v); e[7] = exv16<4>(v); e[8] = exv16<2>(v); e[9] = exv16<1>(v);
    PERM01();
    e[2] = exv16<8>(v); e[3] = exv16<4>(v); e[4] = exv16<2>(v); e[5] = exv16<1>(v);
    PERM12();
    e[0] = exv16<8>(v); e[1] = exv16<4>(v);

    #pragma unroll
    for (int q = 0; q < 10; ++q) {
        float a = e[q];
        #pragma unroll
        for (int o = 16; o; o >>= 1) a += __shfl_xor_sync(0xffffffffu, a, o);
        if (lane == 0) red[q * 2 + w] = a;
    }
    __syncthreads();
    if (tid < 10)
        out[(size_t)b * (NGEN * NQ) + g * NQ + tid] = red[tid * 2] + red[tid * 2 + 1];

    #undef PERM01
    #undef PERM12
    #undef PERM20
}

extern "C" void kernel_launch(void* const* d_in, const int* in_sizes, int n_in,
                              void* d_out, int out_size) {
    const float* noise = (const float*)d_in[0];   // (BATCH, NQ) fp32
    const float* qp    = (const float*)d_in[1];   // (NGEN, QDEPTH, NQ) fp32
    float* out = (float*)d_out;                   // (BATCH, NGEN*NQ) fp32

    int batch  = in_sizes[0] / NQ;
    int blocks = batch * NGEN;                    // one block (2 warps) per circuit
    qgen2w<<<blocks, 64>>>(noise, qp, out, batch);
}

// round 17
// speedup vs baseline: 1.4620x; 1.4620x over previous
#include <cuda_runtime.h>

typedef unsigned long long u64;

#define NQ     10
#define NGEN   4
#define QDEPTH 6
#define WPB    4   // warps per block

// Parity-of-adjacent-pairs mask for 5-bit k: bit k = popc(k & (k>>1)) & 1.
#define MK_CONST 0x4748B848u
constexpr unsigned mk_check() {
    unsigned m = 0;
    for (int k = 0; k < 32; ++k) {
        int p = 0;
        for (int bb = 0; bb < 4; ++bb) p ^= ((k >> bb) & 1) & ((k >> (bb + 1)) & 1);
        m |= (unsigned)p << k;
    }
    return m;
}
static_assert(mk_check() == MK_CONST, "MK mask mismatch");

// ---- packed f32x2 helpers (SASS FFMA2 — PTX-only on sm_103a) ----
__device__ __forceinline__ u64 fma2(u64 a, u64 b, u64 c) {
    u64 d; asm("fma.rn.f32x2 %0, %1, %2, %3;" : "=l"(d) : "l"(a), "l"(b), "l"(c)); return d;
}
__device__ __forceinline__ u64 pack2(float lo, float hi) {
    u64 d; asm("mov.b64 %0, {%1, %2};" : "=l"(d) : "f"(lo), "f"(hi)); return d;
}
__device__ __forceinline__ void unpack2(u64 v, float& lo, float& hi) {
    asm("mov.b64 {%0, %1}, %2;" : "=f"(lo), "=f"(hi) : "l"(v));
}

// complex multiply, scalar float2 form: 4 FFMA-class ops
__device__ __forceinline__ float2 cmul(float2 a, float2 b) {
    return make_float2(fmaf(-a.y, b.y, a.x * b.x),
                       fmaf( a.y, b.x, a.x * b.y));
}

// ---- RY via shear/lifting: 3 fma2 per pair. Rotation phi: nt=(-t,-t), sn=(s,s).
template<int M>
__device__ __forceinline__ void ry2_shear(u64 (&v)[32], u64 nt, u64 sn) {
    #pragma unroll
    for (int k = 0; k < 32; ++k) if (!(k & M)) {
        const int j = k | M;
        u64 a0 = v[k], a1 = v[j];
        a0 = fma2(nt, a1, a0);
        a1 = fma2(sn, a0, a1);
        a0 = fma2(nt, a1, a0);
        v[k] = a0; v[j] = a1;
    }
}

template<int M>
__device__ __forceinline__ float exv(const u64 (&v)[32]) {
    u64 acc0 = 0ull, acc1 = 0ull, acc2 = 0ull, acc3 = 0ull;
    #pragma unroll
    for (int k = 0; k < 32; k += 4) {
        acc0 = fma2(v[k + 0], v[(k + 0) ^ M], acc0);
        acc1 = fma2(v[k + 1], v[(k + 1) ^ M], acc1);
        acc2 = fma2(v[k + 2], v[(k + 2) ^ M], acc2);
        acc3 = fma2(v[k + 3], v[(k + 3) ^ M], acc3);
    }
    float l0, h0, l1, h1, l2, h2, l3, h3;
    unpack2(acc0, l0, h0); unpack2(acc1, l1, h1);
    unpack2(acc2, l2, h2); unpack2(acc3, l3, h3);
    return (l0 + h0) + (l1 + h1) + ((l2 + h2) + (l3 + h3));
}

// CZ-chain diagonal: predicated sign flip
__device__ __forceinline__ void cz_apply(u64 (&v)[32], unsigned sgn) {
    #pragma unroll
    for (int k = 0; k < 32; ++k)
        if (sgn & (1u << k)) v[k] ^= 0x8000000080000000ull;
}

// 32x32 warp transpose through padded smem (stride-34 u64 rows).
__device__ __forceinline__ void transpose(u64 (&v)[32], u64* t, unsigned lane) {
    __syncwarp();
    #pragma unroll
    for (int r = 0; r < 32; r += 2)
        *reinterpret_cast<ulonglong2*>(t + lane * 34u + r) = make_ulonglong2(v[r], v[r + 1]);
    __syncwarp();
    #pragma unroll
    for (int k = 0; k < 32; ++k)
        v[k] = t[k * 34u + lane];
}

// 5 shear-RY gates; pre-packed u64 consts (one LDS.64 broadcast each)
__device__ __forceinline__ void half5(u64 (&v)[32],
                                      const u64* __restrict__ nt2,
                                      const u64* __restrict__ sn2,
                                      int base) {
    ry2_shear<16>(v, nt2[base + 0], sn2[base + 0]);
    ry2_shear<8>(v,  nt2[base + 1], sn2[base + 1]);
    ry2_shear<4>(v,  nt2[base + 2], sn2[base + 2]);
    ry2_shear<2>(v,  nt2[base + 3], sn2[base + 3]);
    ry2_shear<1>(v,  nt2[base + 4], sn2[base + 4]);
}

// ===== Fused kernel: one warp per (b, g) =====
// Layout A: i = lane*32 + k (register wires 5..9; M=16..1 <-> wires 5..9)
// Layout B: i = k*32 + lane (register wires 0..4; M=16..1 <-> wires 0..4)
__global__ void __launch_bounds__(32 * WPB, 4)
qgen_fused(const float* __restrict__ noise,
           const float* __restrict__ qp,
           float* __restrict__ out, int batch)
{
    __shared__ u64    tile[WPB][32 * 34];
    __shared__ u64    tnt2[WPB][64], tsn2[WPB][64];  // tail RY shear (rows 1..5 used)
    __shared__ float2 WV[WPB][NQ][2];                // per-wire product-state 2-vectors

    const unsigned lane = threadIdx.x & 31u;
    const unsigned w    = threadIdx.x >> 5;
    const unsigned wid  = blockIdx.x * WPB + w;
    const unsigned b    = wid >> 2;          // 4 gens of one sample share a block
    const unsigned g    = wid & 3u;
    if ((int)b >= batch) return;
    u64* t = tile[w];

    // ---- lane-parallel const precompute ----
    const float* wg = qp + g * (QDEPTH * NQ);
    {
        // tail shear consts for layer rows 1..5 (idx 10..59)
        float s4, c4;
        {   // idx 10..41
            float a = wg[10 + lane];
            __sincosf(0.25f * a, &s4, &c4);
            float tt = __fdividef(s4, c4);
            float ss = 2.0f * s4 * c4;
            tnt2[w][10 + lane] = pack2(-tt, -tt);
            tsn2[w][10 + lane] = pack2(ss, ss);
        }
        if (lane < 18) {   // idx 42..59
            float a = wg[42 + lane];
            __sincosf(0.25f * a, &s4, &c4);
            float tt = __fdividef(s4, c4);
            float ss = 2.0f * s4 * c4;
            tnt2[w][42 + lane] = pack2(-tt, -tt);
            tsn2[w][42 + lane] = pack2(ss, ss);
        }
        if (lane < NQ) {
            // per-wire 2-vector after RY(n) RX(n) RY(w_row0):
            //   RY(n)|0> = (a1, b1), a1=cos(n/2), b1=sin(n/2)
            //   RX(n):  x = a1^2 - i b1^2 ; y = a1 b1 - i a1 b1
            //   RY(w):  alpha = cw x - sw y ; beta = sw x + cw y
            float n  = noise[(size_t)b * NQ + lane];
            float w1 = wg[lane];
            float a1, b1, sw, cw;
            __sincosf(0.5f * n,  &b1, &a1);
            __sincosf(0.5f * w1, &sw, &cw);
            float xr = a1 * a1, xi = -b1 * b1;
            float yr = a1 * b1, yi = -yr;
            WV[w][lane][0] = make_float2(fmaf(cw, xr, -sw * yr), fmaf(cw, xi, -sw * yi));
            WV[w][lane][1] = make_float2(fmaf(sw, xr,  cw * yr), fmaf(sw, xi,  cw * yi));
        }
    }
    __syncwarp();
    const u64* NT = tnt2[w];
    const u64* SN = tsn2[w];

    const unsigned pL   = (__popc(lane & (lane >> 1)) & 1) ? 0xFFFFFFFFu : 0u;
    const unsigned sgnA = MK_CONST ^ pL ^ ((lane & 1u)        ? 0xFFFF0000u : 0u);
    const unsigned sgnB = MK_CONST ^ pL ^ (((lane >> 4) & 1u) ? 0xAAAAAAAAu : 0u);

    // ---- build product state directly in layout B ----
    // i = k<<5 | lane. Lane bit j <-> wire 9-j (j=4..0 -> wires 5..9).
    // Reg bit j <-> wire 4-j (bit4 -> wire0 ... bit0 -> wire4).
    u64 v[32];
    {
        const float2 (*W)[2] = WV[w];
        float2 L = W[5][(lane >> 4) & 1];
        L = cmul(L, W[6][(lane >> 3) & 1]);
        L = cmul(L, W[7][(lane >> 2) & 1]);
        L = cmul(L, W[8][(lane >> 1) & 1]);
        L = cmul(L, W[9][lane & 1]);

        float2 LA[4];     // L * (wire0 ⊗ wire1)
        #pragma unroll
        for (int j = 0; j < 4; ++j)
            LA[j] = cmul(L, cmul(W[0][j >> 1], W[1][j & 1]));

        float2 T34[4];    // wire2 ⊗ wire3
        #pragma unroll
        for (int j = 0; j < 4; ++j)
            T34[j] = cmul(W[2][j >> 1], W[3][j & 1]);

        float2 B3[8];     // ⊗ wire4
        #pragma unroll
        for (int j = 0; j < 8; ++j)
            B3[j] = cmul(T34[j >> 1], W[4][j & 1]);

        #pragma unroll
        for (int k = 0; k < 32; ++k) {
            float2 a = cmul(LA[k >> 3], B3[k & 7]);
            v[k] = pack2(a.x, a.y);
        }
    }

    // layer 0's CZ (state in layout B)
    cz_apply(v, sgnB);

    // ---- layers 1..5 ----
    // l=1: B(0-4) T A(5-9) czA | l=2: A(5-9) T B(0-4) czB | l=3,4 repeat | l=5: B(0-4) T A(5-9) czA
    #pragma unroll
    for (int l = 1; l <= 4; l += 2) {
        const int o = l * NQ;
        half5(v, NT, SN, o + 0);       // layout B: wires 0..4
        transpose(v, t, lane);         // -> A
        half5(v, NT, SN, o + 5);       // wires 5..9
        cz_apply(v, sgnA);
        const int o2 = o + NQ;
        half5(v, NT, SN, o2 + 5);      // layout A: wires 5..9
        transpose(v, t, lane);         // -> B
        half5(v, NT, SN, o2 + 0);      // wires 0..4
        cz_apply(v, sgnB);
    }
    {
        const int o = 5 * NQ;
        half5(v, NT, SN, o + 0);       // layout B: wires 0..4
        transpose(v, t, lane);         // -> A
        half5(v, NT, SN, o + 5);       // wires 5..9
        cz_apply(v, sgnA);
    }

    // ---- expectations (state in layout A) ----
    float e[10];
    e[5] = exv<16>(v); e[6] = exv<8>(v); e[7] = exv<4>(v);   // layout A: wires 5..9
    e[8] = exv<2>(v);  e[9] = exv<1>(v);
    transpose(v, t, lane);                                    // -> B
    e[0] = exv<16>(v); e[1] = exv<8>(v); e[2] = exv<4>(v);   // wires 0..4
    e[3] = exv<2>(v);  e[4] = exv<1>(v);

    #pragma unroll
    for (int q = 0; q < 10; ++q) {
        float a = e[q];
        #pragma unroll
        for (int o = 16; o; o >>= 1) a += __shfl_xor_sync(0xffffffffu, a, o);
        e[q] = a;
    }
    if (lane == 0) {
        float* ob = out + (size_t)b * (NGEN * NQ) + (size_t)g * NQ;
        #pragma unroll
        for (int q = 0; q < 10; ++q) ob[q] = e[q];
    }
}

extern "C" void kernel_launch(void* const* d_in, const int* in_sizes, int n_in,
                              void* d_out, int out_size) {
    const float* noise = (const float*)d_in[0];   // (BATCH, NQ) fp32
    const float* qp    = (const float*)d_in[1];   // (NGEN, QDEPTH, NQ) fp32
    float* out = (float*)d_out;                   // (BATCH, NGEN*NQ) fp32

    int batch  = in_sizes[0] / NQ;
    int warps  = batch * NGEN;
    int blocks = (warps + WPB - 1) / WPB;
    qgen_fused<<<blocks, 32 * WPB>>>(noise, qp, out, batch);
}